// round 1
// baseline (speedup 1.0000x reference)
#include <cuda_runtime.h>

// SCL polar decoder, neural-MLP variant.
// One block per batch element (B=128 blocks, 256 threads). Entire tree
// recursion runs inside a single kernel (template-unrolled DFS, depth 6).
// All MLP math in fp32 to match JAX fp32 reference decisions exactly.

#define NLIST 8
#define DE    64
#define HD    256
#define DU    16
#define NB    128
#define NTOT  64

// ---------------- global scratch (static; no allocation) ----------------
// e tensors per tree level, per batch: level k holds [8][64>>k][64] floats.
__device__ float g_E[NB][65024];

struct Params {
  const float *Wo1, *bo1, *Wo2, *bo2;
  const float *Wc1, *bc1, *Wc2, *bc2;
  const float *Wb1, *bb1, *Wb2, *bb2;
  const float *Wllr, *bllr, *emb;
};

__host__ __device__ constexpr int EOFFc(int k){ int o=0; for(int i=0;i<k;i++) o += 8*64*(64>>i); return o; }
__host__ __device__ constexpr int OOFFc(int k){ int o=0; for(int i=0;i<k;i++) o += 8*(64>>i);    return o; }
__host__ __device__ constexpr int SOFFc(int k){ int o=0; for(int i=0;i<k;i++) o += 4*(64>>i);    return o; }

struct Smem {
  float A[16*144];     // layer-1 input staging tile (16 rows x K<=144)
  float Bh[16*256];    // layer-1 output (hidden) tile, relu'd
  int   Uout[1016];    // per-level current u-hat outputs  [8][N_k]
  int   Xout[1016];    // per-level current partial-sum bits
  float Lout[1016];    // per-level current llr outputs
  int   U1[504];       // left-child saves [8][N_k/2] per level
  int   X1[504];
  float L1[504];
  int   Ord1[48];      // per-level order from left child
  int   Ord2[8];
  int   Ret[8];        // order returned by most recent child call
  float Pm[8];
  float Llr[8];
  float Abs[8];
  int   Hd[8];
};

// ---------------- fused 2-layer MLP: K -> 256 -> 64 ----------------
// R rows total, tiled by 16. Layer-1 register tiling: each thread owns
// 4 hidden units x 4 rows (16 FMA per 4 LDG + 4 LDS). Hidden tile stays
// in smem; layer-2 consumes it directly. Weights stream from L2.
template<typename F>
__device__ void run_mlp(Smem& sm, int R, int K,
    const float* __restrict__ W1, const float* __restrict__ b1,
    const float* __restrict__ W2, const float* __restrict__ b2,
    float* __restrict__ Eout, F loadX)
{
  const int tid = threadIdx.x;
  const int hg  = tid & 63;   // hidden group / output column
  const int rg  = tid >> 6;   // row group (4 groups x 4 rows)
  for (int r0 = 0; r0 < R; r0 += 16) {
    const int T = min(16, R - r0);
    __syncthreads();
    // stage input rows into smem
    for (int idx = tid; idx < T*K; idx += 256) {
      int r = idx / K;
      int k = idx - r*K;
      sm.A[r*K + k] = loadX(r0 + r, k);
    }
    __syncthreads();
    // ---- layer 1 ----
    {
      float a0[4], a1[4], a2[4], a3[4];
      const float bb0 = b1[hg], bb1 = b1[hg+64], bb2 = b1[hg+128], bb3 = b1[hg+192];
      #pragma unroll
      for (int j=0;j<4;j++){ a0[j]=bb0; a1[j]=bb1; a2[j]=bb2; a3[j]=bb3; }
      #pragma unroll 2
      for (int k=0;k<K;k++){
        float w0=W1[k*HD+hg], w1=W1[k*HD+hg+64], w2=W1[k*HD+hg+128], w3=W1[k*HD+hg+192];
        #pragma unroll
        for (int j=0;j<4;j++){
          float x = sm.A[(rg*4+j)*K + k];
          a0[j] += w0*x; a1[j] += w1*x; a2[j] += w2*x; a3[j] += w3*x;
        }
      }
      #pragma unroll
      for (int j=0;j<4;j++){
        int r = rg*4+j;
        sm.Bh[r*HD+hg]     = fmaxf(a0[j],0.f);
        sm.Bh[r*HD+hg+64]  = fmaxf(a1[j],0.f);
        sm.Bh[r*HD+hg+128] = fmaxf(a2[j],0.f);
        sm.Bh[r*HD+hg+192] = fmaxf(a3[j],0.f);
      }
    }
    __syncthreads();
    // ---- layer 2 (256 -> 64), no relu ----
    {
      float acc[4];
      #pragma unroll
      for (int j=0;j<4;j++) acc[j] = b2[hg];
      #pragma unroll 4
      for (int k=0;k<HD;k++){
        float w = W2[k*64+hg];
        #pragma unroll
        for (int j=0;j<4;j++) acc[j] += sm.Bh[(rg*4+j)*HD + k]*w;
      }
      #pragma unroll
      for (int j=0;j<4;j++){
        int r = rg*4+j;
        if (r < T) Eout[(r0+r)*64 + hg] = acc[j];
      }
    }
  }
  __syncthreads();
}

// ---------------- leaf (N==1): llr head + path-metric selection ----------------
__device__ void do_leaf(Smem& sm, int b, int leaf, const Params& P, const int* __restrict__ f)
{
  const int tid = threadIdx.x, warp = tid>>5, lane = tid&31;
  constexpr int E6 = EOFFc(6);
  constexpr int O6 = OOFFc(6);
  if (warp < 8) {
    const float* e = &g_E[b][E6 + warp*64];
    float z0 = 0.f, z1 = 0.f;
    for (int c = lane; c < 64; c += 32){
      float v = e[c];
      z0 += v*P.Wllr[c*2];
      z1 += v*P.Wllr[c*2+1];
    }
    #pragma unroll
    for (int off=16; off; off>>=1){
      z0 += __shfl_xor_sync(0xffffffffu, z0, off);
      z1 += __shfl_xor_sync(0xffffffffu, z1, off);
    }
    if (lane == 0){
      z0 += P.bllr[0]; z1 += P.bllr[1];
      // softmax(2) -> p1, clip, llr  (matches jax.nn.softmax numerics)
      float m  = fmaxf(z0, z1);
      float e0 = expf(z0 - m), e1 = expf(z1 - m);
      float p1 = e1 / (e0 + e1);
      p1 = fminf(fmaxf(p1, 1e-6f), 1.0f - 1e-6f);
      float llr = logf(p1) - logf(1.0f - p1);
      sm.Llr[warp] = llr;
      sm.Abs[warp] = fabsf(llr);
      sm.Hd[warp]  = (z1 > z0) ? 1 : 0;   // argmax, ties -> 0
    }
  }
  __syncthreads();
  if (tid == 0){
    int fv = f[leaf];          // frozen pattern identical across batch
    if (fv != 2){
      // frozen: keep list order, penalize mismatches
      for (int l=0;l<8;l++){
        sm.Xout[O6+l] = fv; sm.Uout[O6+l] = fv;
        sm.Lout[O6+l] = sm.Llr[l];
        if (sm.Hd[l] != fv) sm.Pm[l] = sm.Pm[l] + sm.Abs[l];
        sm.Ret[l] = l;
      }
    } else {
      // info bit: duplicate paths, keep 8 smallest pm (tie -> lower index),
      // survivors emitted in ascending original index (matches sort+argsort).
      float pd[16]; int hd16[16];
      for (int l=0;l<8;l++){
        pd[l]    = sm.Pm[l];
        pd[l+8]  = sm.Pm[l] + sm.Abs[l];
        hd16[l]  = sm.Hd[l];
        hd16[l+8]= 1 - sm.Hd[l];
      }
      float np[8]; int j = 0;
      for (int i=0;i<16;i++){
        int rank = 0;
        for (int q=0;q<16;q++)
          if (pd[q] < pd[i] || (pd[q] == pd[i] && q < i)) rank++;
        if (rank < 8){
          sm.Xout[O6+j] = hd16[i];
          sm.Uout[O6+j] = hd16[i];
          np[j] = pd[i];
          sm.Ret[j] = i & 7;
          j++;
        }
      }
      for (int l=0;l<8;l++){ sm.Pm[l] = np[l]; sm.Lout[O6+l] = sm.Llr[l]; }
    }
  }
  __syncthreads();
}

// ---------------- tree recursion (compile-time unrolled) ----------------
template<int NK, int LVL>
__device__ void decode_node(Smem& sm, int b, int leaf_base, const Params& P, const int* __restrict__ f)
{
  if constexpr (NK == 1) {
    do_leaf(sm, b, leaf_base, P, f);
  } else {
    constexpr int half = NK/2;
    constexpr int R    = 8*half;
    constexpr int EK = EOFFc(LVL),  EN = OOFFc(0)*0 + EOFFc(LVL+1);
    constexpr int ON = OOFFc(LVL+1);
    constexpr int OK = OOFFc(LVL);
    constexpr int SK = SOFFc(LVL);
    float* Ek = &g_E[b][EK];
    float* En = &g_E[b][EN];

    // chk MLP: input = concat(e_odd, e_even), K=128
    run_mlp(sm, R, 2*DE, P.Wc1, P.bc1, P.Wc2, P.bc2, En,
      [&](int r, int k)->float {
        int l = r / half, t = r - l*half;
        int pos = 2*t + (k >> 6);
        return Ek[(l*NK + pos)*64 + (k & 63)];
      });

    decode_node<half, LVL+1>(sm, b, leaf_base, P, f);

    // save left outputs + order before right child overwrites them
    __syncthreads();
    for (int idx = threadIdx.x; idx < R; idx += 256){
      sm.U1[SK+idx] = sm.Uout[ON+idx];
      sm.X1[SK+idx] = sm.Xout[ON+idx];
      sm.L1[SK+idx] = sm.Lout[ON+idx];
    }
    if (threadIdx.x < 8) sm.Ord1[LVL*8 + threadIdx.x] = sm.Ret[threadIdx.x];
    __syncthreads();

    // bit MLP: input = concat(e_odd[ord1], e_even[ord1], emb[u1hp]), K=144
    run_mlp(sm, R, 2*DE+DU, P.Wb1, P.bb1, P.Wb2, P.bb2, En,
      [&](int r, int k)->float {
        int l = r / half, t = r - l*half;
        if (k < 128){
          int ol  = sm.Ord1[LVL*8 + l];
          int pos = 2*t + (k >> 6);
          return Ek[(ol*NK + pos)*64 + (k & 63)];
        }
        int bit = sm.X1[SK + l*half + t];
        return P.emb[bit*DU + (k - 128)];
      });

    decode_node<half, LVL+1>(sm, b, leaf_base + half, P, f);

    // combine: gather left by ord2, concat u/llr, butterfly the hard bits
    __syncthreads();
    if (threadIdx.x < 8) sm.Ord2[threadIdx.x] = sm.Ret[threadIdx.x];
    __syncthreads();
    for (int idx = threadIdx.x; idx < R; idx += 256){
      int l = idx / half, t = idx - l*half;
      int o2 = sm.Ord2[l];
      int   u1 = sm.U1[SK + o2*half + t];
      int   x1 = sm.X1[SK + o2*half + t];
      float l1 = sm.L1[SK + o2*half + t];
      int   u2 = sm.Uout[ON + idx];
      int   x2 = sm.Xout[ON + idx];
      float l2 = sm.Lout[ON + idx];
      sm.Uout[OK + l*NK + t]          = u1;
      sm.Uout[OK + l*NK + half + t]   = u2;
      sm.Lout[OK + l*NK + t]          = l1;
      sm.Lout[OK + l*NK + half + t]   = l2;
      sm.Xout[OK + l*NK + 2*t]        = (x1 + x2) & 1;
      sm.Xout[OK + l*NK + 2*t + 1]    = x2;
    }
    __syncthreads();
    if (threadIdx.x < 8) sm.Ret[threadIdx.x] = sm.Ord1[LVL*8 + sm.Ord2[threadIdx.x]];
    __syncthreads();
  }
}

__global__ void __launch_bounds__(256, 1)
scl_kernel(Params P, const float* __restrict__ y, const int* __restrict__ f,
           float* __restrict__ out, int out_size)
{
  __shared__ Smem sm;
  const int b = blockIdx.x, tid = threadIdx.x;
  if (tid < 8) sm.Pm[tid] = (tid == 0) ? 0.f : 1e8f;
  __syncthreads();

  // observation MLP (K=4) -> E0 list 0
  run_mlp(sm, 64, 4, P.Wo1, P.bo1, P.Wo2, P.bo2, &g_E[b][0],
    [&](int r, int k)->float { return y[(b*64 + r)*4 + k]; });

  // replicate E0 across the 8 lists
  for (int idx = tid; idx < 7*4096; idx += 256)
    g_E[b][4096 + idx] = g_E[b][idx & 4095];
  __syncthreads();

  decode_node<64, 0>(sm, b, 0, P, f);

  if (tid == 0){
    int best = 0; float bv = sm.Pm[0];
    for (int l=1;l<8;l++) if (sm.Pm[l] < bv){ bv = sm.Pm[l]; best = l; }
    sm.Ord2[0] = best;
  }
  __syncthreads();
  const int best = sm.Ord2[0];

  // outputs: uhat (B,64) then llr (B,8,64), both as float
  if (out_size >= 8192 + 65536){
    for (int t = tid; t < 64; t += 256)
      out[b*64 + t] = (float)sm.Uout[best*64 + t];
    for (int idx = tid; idx < 512; idx += 256)
      out[8192 + b*512 + idx] = sm.Lout[idx];
  } else if (out_size == 8192){
    for (int t = tid; t < 64; t += 256)
      out[b*64 + t] = (float)sm.Uout[best*64 + t];
  } else {
    for (int idx = tid; idx < 512 && (b*512 + idx) < out_size; idx += 256)
      out[b*512 + idx] = sm.Lout[idx];
  }
}

extern "C" void kernel_launch(void* const* d_in, const int* in_sizes, int n_in,
                              void* d_out, int out_size)
{
  Params P;
  const float* y  = (const float*)d_in[0];
  const int*   f  = (const int*)  d_in[1];
  P.Wo1  = (const float*)d_in[2];
  P.bo1  = (const float*)d_in[3];
  P.Wo2  = (const float*)d_in[4];
  P.bo2  = (const float*)d_in[5];
  P.Wc1  = (const float*)d_in[6];
  P.bc1  = (const float*)d_in[7];
  P.Wc2  = (const float*)d_in[8];
  P.bc2  = (const float*)d_in[9];
  P.Wb1  = (const float*)d_in[10];
  P.bb1  = (const float*)d_in[11];
  P.Wb2  = (const float*)d_in[12];
  P.bb2  = (const float*)d_in[13];
  P.Wllr = (const float*)d_in[14];
  P.bllr = (const float*)d_in[15];
  P.emb  = (const float*)d_in[16];

  scl_kernel<<<NB, 256>>>(P, y, f, (float*)d_out, out_size);
}

// round 2
// speedup vs baseline: 1.6220x; 1.6220x over previous
#include <cuda_runtime.h>

// SCL polar decoder, neural-MLP variant. Round 2:
//  - 512 threads/block, 32-row MLP tiles, float4 weight loads
//  - transposed hidden tile (stride 33) -> conflict-free layer-2 LDS
//  - uniform-list elimination before first info leaf
//  - warp-parallel leaf top-k selection
// fp32 throughout, accumulation order identical to round 1 (bit-exact).

#define NLIST 8
#define DE    64
#define HD    256
#define DU    16
#define NB    128

__device__ float g_E[NB][65024];

struct Params {
  const float *Wo1, *bo1, *Wo2, *bo2;
  const float *Wc1, *bc1, *Wc2, *bc2;
  const float *Wb1, *bb1, *Wb2, *bb2;
  const float *Wllr, *bllr, *emb;
};

__host__ __device__ constexpr int EOFFc(int k){ int o=0; for(int i=0;i<k;i++) o += 8*64*(64>>i); return o; }
__host__ __device__ constexpr int OOFFc(int k){ int o=0; for(int i=0;i<k;i++) o += 8*(64>>i);    return o; }
__host__ __device__ constexpr int SOFFc(int k){ int o=0; for(int i=0;i<k;i++) o += 4*(64>>i);    return o; }

struct Smem {
  float A[32*145];     // input staging, stride K+1 (max K=144)
  float Bh[256*33];    // hidden tile TRANSPOSED: [h][r], stride 33
  int   Uout[1016];
  int   Xout[1016];
  float Lout[1016];
  int   U1[504];
  int   X1[504];
  float L1[504];
  int   Ord1[48];
  int   Ord2[8];
  int   Ret[8];
  float Pm[8];
  float PmNew[8];
  float Llr[8];
  float Abs[8];
  int   Hd[8];
  int   first_info;
};

// ---------------- fused 2-layer MLP: K -> 256 -> 64 ----------------
template<int K, typename F>
__device__ void run_mlp(Smem& sm, int R,
    const float* __restrict__ W1, const float* __restrict__ b1,
    const float* __restrict__ W2, const float* __restrict__ b2,
    float* __restrict__ Eout, F loadX)
{
  constexpr int KP = K + 1;
  const int tid = threadIdx.x;
  const int hq  = tid & 63;        // hidden quad: cols 4hq..4hq+3
  const int rg  = tid >> 6;        // row group (8 groups x 4 rows)
  const int cq  = tid & 15;        // layer-2 col quad
  const int r2  = tid >> 4;        // layer-2 row (0..31)
  const float4 bb1 = ((const float4*)b1)[hq];
  const float4 bb2 = ((const float4*)b2)[cq];

  for (int r0 = 0; r0 < R; r0 += 32) {
    const int T = min(32, R - r0);
    __syncthreads();
    for (int idx = tid; idx < T*K; idx += 512) {
      int r = idx / K, k = idx - r*K;
      sm.A[r*KP + k] = loadX(r0 + r, k);
    }
    __syncthreads();
    // ---- layer 1: 16 FMA per (1 LDG.128 + 4 LDS) ----
    {
      float4 a0 = bb1, a1 = bb1, a2 = bb1, a3 = bb1;
      const float* Ab = &sm.A[rg*4*KP];
      #pragma unroll 4
      for (int k = 0; k < K; k++){
        float4 w = ((const float4*)(W1 + k*HD))[hq];
        float x0 = Ab[k], x1 = Ab[KP + k], x2 = Ab[2*KP + k], x3 = Ab[3*KP + k];
        a0.x += w.x*x0; a0.y += w.y*x0; a0.z += w.z*x0; a0.w += w.w*x0;
        a1.x += w.x*x1; a1.y += w.y*x1; a1.z += w.z*x1; a1.w += w.w*x1;
        a2.x += w.x*x2; a2.y += w.y*x2; a2.z += w.z*x2; a2.w += w.w*x2;
        a3.x += w.x*x3; a3.y += w.y*x3; a3.z += w.z*x3; a3.w += w.w*x3;
      }
      const int r = rg*4;
      float* B0 = &sm.Bh[(4*hq)*33 + r];
      B0[0]    = fmaxf(a0.x,0.f); B0[1]      = fmaxf(a1.x,0.f); B0[2]      = fmaxf(a2.x,0.f); B0[3]      = fmaxf(a3.x,0.f);
      B0[33]   = fmaxf(a0.y,0.f); B0[33+1]   = fmaxf(a1.y,0.f); B0[33+2]   = fmaxf(a2.y,0.f); B0[33+3]   = fmaxf(a3.y,0.f);
      B0[66]   = fmaxf(a0.z,0.f); B0[66+1]   = fmaxf(a1.z,0.f); B0[66+2]   = fmaxf(a2.z,0.f); B0[66+3]   = fmaxf(a3.z,0.f);
      B0[99]   = fmaxf(a0.w,0.f); B0[99+1]   = fmaxf(a1.w,0.f); B0[99+2]   = fmaxf(a2.w,0.f); B0[99+3]   = fmaxf(a3.w,0.f);
    }
    __syncthreads();
    // ---- layer 2: 4 FMA per (1 LDG.128 + 1 LDS) ----
    {
      float4 acc = bb2;
      #pragma unroll 4
      for (int k = 0; k < HD; k++){
        float  x = sm.Bh[k*33 + r2];
        float4 w = ((const float4*)(W2 + k*64))[cq];
        acc.x += w.x*x; acc.y += w.y*x; acc.z += w.z*x; acc.w += w.w*x;
      }
      if (r2 < T)
        *(float4*)(Eout + (r0+r2)*64 + cq*4) = acc;
    }
  }
  __syncthreads();
}

// broadcast list 0 of a level-E buffer to lists 1..7; cnt = half*64 (pow2)
__device__ void bcast_lists(float* __restrict__ E, int cnt)
{
  for (int idx = threadIdx.x; idx < 7*cnt; idx += 512)
    E[cnt + idx] = E[idx & (cnt - 1)];
  __syncthreads();
}

// ---------------- leaf ----------------
__device__ void do_leaf(Smem& sm, int b, int leaf, const Params& P, const int* __restrict__ f)
{
  const int tid = threadIdx.x, warp = tid>>5, lane = tid&31;
  constexpr int E6 = EOFFc(6);
  constexpr int O6 = OOFFc(6);
  if (warp < 8) {
    const float* e = &g_E[b][E6 + warp*64];
    float z0 = 0.f, z1 = 0.f;
    for (int c = lane; c < 64; c += 32){
      float v = e[c];
      z0 += v*P.Wllr[c*2];
      z1 += v*P.Wllr[c*2+1];
    }
    #pragma unroll
    for (int off=16; off; off>>=1){
      z0 += __shfl_xor_sync(0xffffffffu, z0, off);
      z1 += __shfl_xor_sync(0xffffffffu, z1, off);
    }
    if (lane == 0){
      z0 += P.bllr[0]; z1 += P.bllr[1];
      float m  = fmaxf(z0, z1);
      float e0 = expf(z0 - m), e1 = expf(z1 - m);
      float p1 = e1 / (e0 + e1);
      p1 = fminf(fmaxf(p1, 1e-6f), 1.0f - 1e-6f);
      float llr = logf(p1) - logf(1.0f - p1);
      sm.Llr[warp] = llr;
      sm.Abs[warp] = fabsf(llr);
      sm.Hd[warp]  = (z1 > z0) ? 1 : 0;
    }
  }
  __syncthreads();
  if (warp == 0){
    const int fv = f[leaf];
    if (fv != 2){
      if (lane < 8){
        sm.Xout[O6+lane] = fv; sm.Uout[O6+lane] = fv;
        sm.Lout[O6+lane] = sm.Llr[lane];
        if (sm.Hd[lane] != fv) sm.Pm[lane] += sm.Abs[lane];
        sm.Ret[lane] = lane;
      }
    } else {
      // 16 candidates (8 keep-bit, 8 flip-bit) on lanes 0..15
      float pd = 1e30f; int hd = 0;
      if (lane < 16){
        int l = lane & 7;
        if (lane < 8){ pd = sm.Pm[l];             hd = sm.Hd[l];     }
        else         { pd = sm.Pm[l] + sm.Abs[l]; hd = 1 - sm.Hd[l]; }
      }
      int rank = 0;
      #pragma unroll
      for (int q = 0; q < 16; q++){
        float pq = __shfl_sync(0xffffffffu, pd, q);
        if (pq < pd || (pq == pd && q < lane)) rank++;
      }
      unsigned surv = __ballot_sync(0xffffffffu, lane < 16 && rank < 8);
      if (lane < 16 && rank < 8){
        int pos = __popc(surv & ((1u<<lane) - 1u));
        sm.Xout[O6+pos] = hd; sm.Uout[O6+pos] = hd;
        sm.PmNew[pos]   = pd;
        sm.Ret[pos]     = lane & 7;
      }
      __syncwarp();
      if (lane < 8){ sm.Pm[lane] = sm.PmNew[lane]; sm.Lout[O6+lane] = sm.Llr[lane]; }
    }
  }
  __syncthreads();
}

// ---------------- tree recursion ----------------
template<int NK, int LVL>
__device__ void decode_node(Smem& sm, int b, int leaf_base, const Params& P, const int* __restrict__ f)
{
  if constexpr (NK == 1) {
    do_leaf(sm, b, leaf_base, P, f);
  } else {
    constexpr int half = NK/2;
    constexpr int R    = 8*half;
    constexpr int EK = EOFFc(LVL), EN = EOFFc(LVL+1);
    constexpr int ON = OOFFc(LVL+1);
    constexpr int OK = OOFFc(LVL);
    constexpr int SK = SOFFc(LVL);
    float* Ek = &g_E[b][EK];
    float* En = &g_E[b][EN];

    // chk MLP: uniform across lists until first info leaf is decoded
    const bool uc = (sm.first_info >= leaf_base);
    run_mlp<2*DE>(sm, uc ? half : R, P.Wc1, P.bc1, P.Wc2, P.bc2, En,
      [&](int r, int k)->float {
        int l = r / half, t = r - l*half;
        int pos = 2*t + (k >> 6);
        return Ek[(l*NK + pos)*64 + (k & 63)];
      });
    if (uc) bcast_lists(En, half*64);

    decode_node<half, LVL+1>(sm, b, leaf_base, P, f);

    __syncthreads();
    for (int idx = threadIdx.x; idx < R; idx += 512){
      sm.U1[SK+idx] = sm.Uout[ON+idx];
      sm.X1[SK+idx] = sm.Xout[ON+idx];
      sm.L1[SK+idx] = sm.Lout[ON+idx];
    }
    if (threadIdx.x < 8) sm.Ord1[LVL*8 + threadIdx.x] = sm.Ret[threadIdx.x];
    __syncthreads();

    const bool ub = (sm.first_info >= leaf_base + half);
    run_mlp<2*DE+DU>(sm, ub ? half : R, P.Wb1, P.bb1, P.Wb2, P.bb2, En,
      [&](int r, int k)->float {
        int l = r / half, t = r - l*half;
        if (k < 128){
          int ol  = sm.Ord1[LVL*8 + l];
          int pos = 2*t + (k >> 6);
          return Ek[(ol*NK + pos)*64 + (k & 63)];
        }
        int bit = sm.X1[SK + l*half + t];
        return P.emb[bit*DU + (k - 128)];
      });
    if (ub) bcast_lists(En, half*64);

    decode_node<half, LVL+1>(sm, b, leaf_base + half, P, f);

    __syncthreads();
    if (threadIdx.x < 8) sm.Ord2[threadIdx.x] = sm.Ret[threadIdx.x];
    __syncthreads();
    for (int idx = threadIdx.x; idx < R; idx += 512){
      int l = idx / half, t = idx - l*half;
      int o2 = sm.Ord2[l];
      int   u1 = sm.U1[SK + o2*half + t];
      int   x1 = sm.X1[SK + o2*half + t];
      float l1 = sm.L1[SK + o2*half + t];
      int   u2 = sm.Uout[ON + idx];
      int   x2 = sm.Xout[ON + idx];
      float l2 = sm.Lout[ON + idx];
      sm.Uout[OK + l*NK + t]        = u1;
      sm.Uout[OK + l*NK + half + t] = u2;
      sm.Lout[OK + l*NK + t]        = l1;
      sm.Lout[OK + l*NK + half + t] = l2;
      sm.Xout[OK + l*NK + 2*t]      = (x1 + x2) & 1;
      sm.Xout[OK + l*NK + 2*t + 1]  = x2;
    }
    __syncthreads();
    if (threadIdx.x < 8) sm.Ret[threadIdx.x] = sm.Ord1[LVL*8 + sm.Ord2[threadIdx.x]];
    __syncthreads();
  }
}

__global__ void __launch_bounds__(512, 1)
scl_kernel(Params P, const float* __restrict__ y, const int* __restrict__ f,
           float* __restrict__ out, int out_size)
{
  extern __shared__ char smem_raw[];
  Smem& sm = *reinterpret_cast<Smem*>(smem_raw);
  const int b = blockIdx.x, tid = threadIdx.x;
  if (tid < 8) sm.Pm[tid] = (tid == 0) ? 0.f : 1e8f;
  if (tid == 0){
    int fi = 64;
    for (int i = 0; i < 64; i++) if (f[i] == 2){ fi = i; break; }
    sm.first_info = fi;
  }
  __syncthreads();

  // observation MLP (K=4) -> E0 list 0
  run_mlp<4>(sm, 64, P.Wo1, P.bo1, P.Wo2, P.bo2, &g_E[b][0],
    [&](int r, int k)->float { return y[(b*64 + r)*4 + k]; });

  // replicate E0 across the 8 lists
  for (int idx = tid; idx < 7*4096; idx += 512)
    g_E[b][4096 + idx] = g_E[b][idx & 4095];
  __syncthreads();

  decode_node<64, 0>(sm, b, 0, P, f);

  if (tid == 0){
    int best = 0; float bv = sm.Pm[0];
    for (int l=1;l<8;l++) if (sm.Pm[l] < bv){ bv = sm.Pm[l]; best = l; }
    sm.Ord2[0] = best;
  }
  __syncthreads();
  const int best = sm.Ord2[0];

  if (out_size >= 8192 + 65536){
    for (int t = tid; t < 64; t += 512)
      out[b*64 + t] = (float)sm.Uout[best*64 + t];
    for (int idx = tid; idx < 512; idx += 512)
      out[8192 + b*512 + idx] = sm.Lout[idx];
  } else if (out_size == 8192){
    for (int t = tid; t < 64; t += 512)
      out[b*64 + t] = (float)sm.Uout[best*64 + t];
  } else {
    for (int idx = tid; idx < 512 && (b*512 + idx) < out_size; idx += 512)
      out[b*512 + idx] = sm.Lout[idx];
  }
}

extern "C" void kernel_launch(void* const* d_in, const int* in_sizes, int n_in,
                              void* d_out, int out_size)
{
  Params P;
  const float* y  = (const float*)d_in[0];
  const int*   f  = (const int*)  d_in[1];
  P.Wo1  = (const float*)d_in[2];
  P.bo1  = (const float*)d_in[3];
  P.Wo2  = (const float*)d_in[4];
  P.bo2  = (const float*)d_in[5];
  P.Wc1  = (const float*)d_in[6];
  P.bc1  = (const float*)d_in[7];
  P.Wc2  = (const float*)d_in[8];
  P.bc2  = (const float*)d_in[9];
  P.Wb1  = (const float*)d_in[10];
  P.bb1  = (const float*)d_in[11];
  P.Wb2  = (const float*)d_in[12];
  P.bb2  = (const float*)d_in[13];
  P.Wllr = (const float*)d_in[14];
  P.bllr = (const float*)d_in[15];
  P.emb  = (const float*)d_in[16];

  cudaFuncSetAttribute(scl_kernel, cudaFuncAttributeMaxDynamicSharedMemorySize,
                       (int)sizeof(Smem));
  scl_kernel<<<NB, 512, sizeof(Smem)>>>(P, y, f, (float*)d_out, out_size);
}

// round 5
// speedup vs baseline: 2.4538x; 1.5128x over previous
#include <cuda_runtime.h>

// SCL polar decoder, neural-MLP variant. Round 5 = Round 4 resubmission
// (round-4 bench died to container infra failure, kernel never ran).
//  - hidden-tile stride 260 (16B-aligned rows) fixes round-3 misaligned STS.128
//  - rows-per-thread template RT {4,2,1} sized to R; layer-2 k-split keeps
//    all 512 threads busy for small tree nodes
//  - row-major hidden tile: conflict-free STS.128 / broadcast LDS
//  - float4 activation loads (A stride K+4), k-loop unroll x2
//  - uniform-list elimination before first info leaf

#define NLIST 8
#define DE    64
#define HD    256
#define DU    16
#define NB    128

__device__ float g_E[NB][65024];

struct Params {
  const float *Wo1, *bo1, *Wo2, *bo2;
  const float *Wc1, *bc1, *Wc2, *bc2;
  const float *Wb1, *bb1, *Wb2, *bb2;
  const float *Wllr, *bllr, *emb;
};

__host__ __device__ constexpr int EOFFc(int k){ int o=0; for(int i=0;i<k;i++) o += 8*64*(64>>i); return o; }
__host__ __device__ constexpr int OOFFc(int k){ int o=0; for(int i=0;i<k;i++) o += 8*(64>>i);    return o; }
__host__ __device__ constexpr int SOFFc(int k){ int o=0; for(int i=0;i<k;i++) o += 4*(64>>i);    return o; }

struct __align__(16) Smem {
  float A[32*148];     // input staging, stride K+4 (16B-aligned rows)
  float Bh[32*260];    // hidden tile row-major [r][h], stride 260 (16B rows)
  float Part[2048];    // layer-2 k-split partials
  int   Uout[1016];
  int   Xout[1016];
  float Lout[1016];
  int   U1[504];
  int   X1[504];
  float L1[504];
  int   Ord1[48];
  int   Ord2[8];
  int   Ret[8];
  float Pm[8];
  float PmNew[8];
  float Llr[8];
  float Abs[8];
  int   Hd[8];
  int   first_info;
};

__device__ __forceinline__ void fma4(float4& a, const float4& w, float x){
  a.x += w.x*x; a.y += w.y*x; a.z += w.z*x; a.w += w.w*x;
}

// ---------------- fused 2-layer MLP: K -> 256 -> 64 ----------------
// RT = rows per thread in layer 1; tile = 8*RT rows (always divides R);
// layer-2 k-split KS = 4/RT groups.
template<int K, int RT, typename F>
__device__ void run_mlp(Smem& sm, int R,
    const float* __restrict__ W1, const float* __restrict__ b1,
    const float* __restrict__ W2, const float* __restrict__ b2,
    float* __restrict__ Eout, F loadX)
{
  constexpr int AST  = K + 4;      // A stride (16B aligned rows)
  constexpr int BST  = 260;        // Bh stride (multiple of 4 -> aligned rows)
  constexpr int TILE = 8*RT;
  constexpr int KS   = 4/RT;       // layer-2 k chunks
  constexpr int KC   = HD/KS;      // k per chunk
  constexpr int TPG  = 128*RT;     // threads per layer-2 group

  const int tid = threadIdx.x;
  const int hq  = tid & 63;        // layer-1 hidden quad
  const int rg  = tid >> 6;        // layer-1 row group (8 groups x RT rows)
  const int g   = tid / TPG;       // layer-2 k-chunk group
  const int loc = tid - g*TPG;
  const int cq  = loc & 15;        // layer-2 col quad
  const int r2  = loc >> 4;        // layer-2 row (0..TILE-1)
  const float4 bb1 = ((const float4*)b1)[hq];
  const float4 bb2 = ((const float4*)b2)[cq];

  for (int r0 = 0; r0 < R; r0 += TILE) {
    __syncthreads();
    for (int idx = tid; idx < TILE*K; idx += 512) {
      int r = idx / K, k = idx - r*K;
      sm.A[r*AST + k] = loadX(r0 + r, k);
    }
    __syncthreads();
    // ---- layer 1 ----
    {
      float4 acc[RT];
      #pragma unroll
      for (int j=0;j<RT;j++) acc[j] = bb1;
      const float* Ab = &sm.A[rg*RT*AST];
      #pragma unroll 2
      for (int k4 = 0; k4 < K; k4 += 4){
        float4 w0 = ((const float4*)(W1 + (k4  )*HD))[hq];
        float4 w1 = ((const float4*)(W1 + (k4+1)*HD))[hq];
        float4 w2 = ((const float4*)(W1 + (k4+2)*HD))[hq];
        float4 w3 = ((const float4*)(W1 + (k4+3)*HD))[hq];
        #pragma unroll
        for (int j=0;j<RT;j++){
          float4 xv = *(const float4*)&Ab[j*AST + k4];
          fma4(acc[j], w0, xv.x);
          fma4(acc[j], w1, xv.y);
          fma4(acc[j], w2, xv.z);
          fma4(acc[j], w3, xv.w);
        }
      }
      #pragma unroll
      for (int j=0;j<RT;j++){
        float4 v;
        v.x = fmaxf(acc[j].x,0.f); v.y = fmaxf(acc[j].y,0.f);
        v.z = fmaxf(acc[j].z,0.f); v.w = fmaxf(acc[j].w,0.f);
        *(float4*)&sm.Bh[(rg*RT + j)*BST + 4*hq] = v;
      }
    }
    __syncthreads();
    // ---- layer 2 (256 -> 64), k-split across KS groups ----
    {
      float4 acc = (KS == 1 || g == 0) ? bb2 : make_float4(0.f,0.f,0.f,0.f);
      const float* Bb = &sm.Bh[r2*BST + g*KC];
      const float* W2b = W2 + g*KC*64;
      #pragma unroll 4
      for (int k = 0; k < KC; k++){
        float  x = Bb[k];
        float4 w = ((const float4*)(W2b + k*64))[cq];
        fma4(acc, w, x);
      }
      if constexpr (KS == 1){
        *(float4*)(Eout + (r0+r2)*64 + cq*4) = acc;
      } else {
        *(float4*)&sm.Part[(g*TILE + r2)*64 + cq*4] = acc;
        __syncthreads();
        if (tid < TPG){
          float4 s = *(const float4*)&sm.Part[r2*64 + cq*4];
          #pragma unroll
          for (int gg = 1; gg < KS; gg++){
            float4 p = *(const float4*)&sm.Part[(gg*TILE + r2)*64 + cq*4];
            s.x += p.x; s.y += p.y; s.z += p.z; s.w += p.w;
          }
          *(float4*)(Eout + (r0+r2)*64 + cq*4) = s;
        }
      }
    }
  }
  __syncthreads();
}

// broadcast list 0 of a level-E buffer to lists 1..7; cnt = half*64 (pow2)
__device__ void bcast_lists(float* __restrict__ E, int cnt)
{
  for (int idx = threadIdx.x; idx < 7*cnt; idx += 512)
    E[cnt + idx] = E[idx & (cnt - 1)];
  __syncthreads();
}

// ---------------- leaf ----------------
__device__ void do_leaf(Smem& sm, int b, int leaf, const Params& P, const int* __restrict__ f)
{
  const int tid = threadIdx.x, warp = tid>>5, lane = tid&31;
  constexpr int E6 = EOFFc(6);
  constexpr int O6 = OOFFc(6);
  if (warp < 8) {
    const float* e = &g_E[b][E6 + warp*64];
    float z0 = 0.f, z1 = 0.f;
    for (int c = lane; c < 64; c += 32){
      float v = e[c];
      z0 += v*P.Wllr[c*2];
      z1 += v*P.Wllr[c*2+1];
    }
    #pragma unroll
    for (int off=16; off; off>>=1){
      z0 += __shfl_xor_sync(0xffffffffu, z0, off);
      z1 += __shfl_xor_sync(0xffffffffu, z1, off);
    }
    if (lane == 0){
      z0 += P.bllr[0]; z1 += P.bllr[1];
      float m  = fmaxf(z0, z1);
      float e0 = expf(z0 - m), e1 = expf(z1 - m);
      float p1 = e1 / (e0 + e1);
      p1 = fminf(fmaxf(p1, 1e-6f), 1.0f - 1e-6f);
      float llr = logf(p1) - logf(1.0f - p1);
      sm.Llr[warp] = llr;
      sm.Abs[warp] = fabsf(llr);
      sm.Hd[warp]  = (z1 > z0) ? 1 : 0;
    }
  }
  __syncthreads();
  if (warp == 0){
    const int fv = f[leaf];
    if (fv != 2){
      if (lane < 8){
        sm.Xout[O6+lane] = fv; sm.Uout[O6+lane] = fv;
        sm.Lout[O6+lane] = sm.Llr[lane];
        if (sm.Hd[lane] != fv) sm.Pm[lane] += sm.Abs[lane];
        sm.Ret[lane] = lane;
      }
    } else {
      float pd = 1e30f; int hd = 0;
      if (lane < 16){
        int l = lane & 7;
        if (lane < 8){ pd = sm.Pm[l];             hd = sm.Hd[l];     }
        else         { pd = sm.Pm[l] + sm.Abs[l]; hd = 1 - sm.Hd[l]; }
      }
      int rank = 0;
      #pragma unroll
      for (int q = 0; q < 16; q++){
        float pq = __shfl_sync(0xffffffffu, pd, q);
        if (pq < pd || (pq == pd && q < lane)) rank++;
      }
      unsigned surv = __ballot_sync(0xffffffffu, lane < 16 && rank < 8);
      if (lane < 16 && rank < 8){
        int pos = __popc(surv & ((1u<<lane) - 1u));
        sm.Xout[O6+pos] = hd; sm.Uout[O6+pos] = hd;
        sm.PmNew[pos]   = pd;
        sm.Ret[pos]     = lane & 7;
      }
      __syncwarp();
      if (lane < 8){ sm.Pm[lane] = sm.PmNew[lane]; sm.Lout[O6+lane] = sm.Llr[lane]; }
    }
  }
  __syncthreads();
}

// ---------------- tree recursion ----------------
template<int NK, int LVL>
__device__ void decode_node(Smem& sm, int b, int leaf_base, const Params& P, const int* __restrict__ f)
{
  if constexpr (NK == 1) {
    do_leaf(sm, b, leaf_base, P, f);
  } else {
    constexpr int half = NK/2;
    constexpr int R    = 8*half;
    constexpr int RTF  = (half >= 4) ? 4 : half;                    // full-list calls
    constexpr int RTU  = (half >= 32) ? 4 : (half >= 16) ? 2 : 1;   // uniform calls
    constexpr int EK = EOFFc(LVL), EN = EOFFc(LVL+1);
    constexpr int ON = OOFFc(LVL+1);
    constexpr int OK = OOFFc(LVL);
    constexpr int SK = SOFFc(LVL);
    float* Ek = &g_E[b][EK];
    float* En = &g_E[b][EN];

    auto chkX = [&](int r, int k)->float {
      int l = r / half, t = r - l*half;
      int pos = 2*t + (k >> 6);
      return Ek[(l*NK + pos)*64 + (k & 63)];
    };
    const bool uc = (sm.first_info >= leaf_base);
    if (uc){
      run_mlp<2*DE, RTU>(sm, half, P.Wc1, P.bc1, P.Wc2, P.bc2, En, chkX);
      bcast_lists(En, half*64);
    } else {
      run_mlp<2*DE, RTF>(sm, R, P.Wc1, P.bc1, P.Wc2, P.bc2, En, chkX);
    }

    decode_node<half, LVL+1>(sm, b, leaf_base, P, f);

    __syncthreads();
    for (int idx = threadIdx.x; idx < R; idx += 512){
      sm.U1[SK+idx] = sm.Uout[ON+idx];
      sm.X1[SK+idx] = sm.Xout[ON+idx];
      sm.L1[SK+idx] = sm.Lout[ON+idx];
    }
    if (threadIdx.x < 8) sm.Ord1[LVL*8 + threadIdx.x] = sm.Ret[threadIdx.x];
    __syncthreads();

    auto bitX = [&](int r, int k)->float {
      int l = r / half, t = r - l*half;
      if (k < 128){
        int ol  = sm.Ord1[LVL*8 + l];
        int pos = 2*t + (k >> 6);
        return Ek[(ol*NK + pos)*64 + (k & 63)];
      }
      int bit = sm.X1[SK + l*half + t];
      return P.emb[bit*DU + (k - 128)];
    };
    const bool ub = (sm.first_info >= leaf_base + half);
    if (ub){
      run_mlp<2*DE+DU, RTU>(sm, half, P.Wb1, P.bb1, P.Wb2, P.bb2, En, bitX);
      bcast_lists(En, half*64);
    } else {
      run_mlp<2*DE+DU, RTF>(sm, R, P.Wb1, P.bb1, P.Wb2, P.bb2, En, bitX);
    }

    decode_node<half, LVL+1>(sm, b, leaf_base + half, P, f);

    __syncthreads();
    if (threadIdx.x < 8) sm.Ord2[threadIdx.x] = sm.Ret[threadIdx.x];
    __syncthreads();
    for (int idx = threadIdx.x; idx < R; idx += 512){
      int l = idx / half, t = idx - l*half;
      int o2 = sm.Ord2[l];
      int   u1 = sm.U1[SK + o2*half + t];
      int   x1 = sm.X1[SK + o2*half + t];
      float l1 = sm.L1[SK + o2*half + t];
      int   u2 = sm.Uout[ON + idx];
      int   x2 = sm.Xout[ON + idx];
      float l2 = sm.Lout[ON + idx];
      sm.Uout[OK + l*NK + t]        = u1;
      sm.Uout[OK + l*NK + half + t] = u2;
      sm.Lout[OK + l*NK + t]        = l1;
      sm.Lout[OK + l*NK + half + t] = l2;
      sm.Xout[OK + l*NK + 2*t]      = (x1 + x2) & 1;
      sm.Xout[OK + l*NK + 2*t + 1]  = x2;
    }
    __syncthreads();
    if (threadIdx.x < 8) sm.Ret[threadIdx.x] = sm.Ord1[LVL*8 + sm.Ord2[threadIdx.x]];
    __syncthreads();
  }
}

__global__ void __launch_bounds__(512, 1)
scl_kernel(Params P, const float* __restrict__ y, const int* __restrict__ f,
           float* __restrict__ out, int out_size)
{
  extern __shared__ char smem_raw[];
  Smem& sm = *reinterpret_cast<Smem*>(smem_raw);
  const int b = blockIdx.x, tid = threadIdx.x;
  if (tid < 8) sm.Pm[tid] = (tid == 0) ? 0.f : 1e8f;
  if (tid == 0){
    int fi = 64;
    for (int i = 0; i < 64; i++) if (f[i] == 2){ fi = i; break; }
    sm.first_info = fi;
  }
  __syncthreads();

  run_mlp<4, 4>(sm, 64, P.Wo1, P.bo1, P.Wo2, P.bo2, &g_E[b][0],
    [&](int r, int k)->float { return y[(b*64 + r)*4 + k]; });

  for (int idx = tid; idx < 7*4096; idx += 512)
    g_E[b][4096 + idx] = g_E[b][idx & 4095];
  __syncthreads();

  decode_node<64, 0>(sm, b, 0, P, f);

  if (tid == 0){
    int best = 0; float bv = sm.Pm[0];
    for (int l=1;l<8;l++) if (sm.Pm[l] < bv){ bv = sm.Pm[l]; best = l; }
    sm.Ord2[0] = best;
  }
  __syncthreads();
  const int best = sm.Ord2[0];

  if (out_size >= 8192 + 65536){
    for (int t = tid; t < 64; t += 512)
      out[b*64 + t] = (float)sm.Uout[best*64 + t];
    for (int idx = tid; idx < 512; idx += 512)
      out[8192 + b*512 + idx] = sm.Lout[idx];
  } else if (out_size == 8192){
    for (int t = tid; t < 64; t += 512)
      out[b*64 + t] = (float)sm.Uout[best*64 + t];
  } else {
    for (int idx = tid; idx < 512 && (b*512 + idx) < out_size; idx += 512)
      out[b*512 + idx] = sm.Lout[idx];
  }
}

extern "C" void kernel_launch(void* const* d_in, const int* in_sizes, int n_in,
                              void* d_out, int out_size)
{
  Params P;
  const float* y  = (const float*)d_in[0];
  const int*   f  = (const int*)  d_in[1];
  P.Wo1  = (const float*)d_in[2];
  P.bo1  = (const float*)d_in[3];
  P.Wo2  = (const float*)d_in[4];
  P.bo2  = (const float*)d_in[5];
  P.Wc1  = (const float*)d_in[6];
  P.bc1  = (const float*)d_in[7];
  P.Wc2  = (const float*)d_in[8];
  P.bc2  = (const float*)d_in[9];
  P.Wb1  = (const float*)d_in[10];
  P.bb1  = (const float*)d_in[11];
  P.Wb2  = (const float*)d_in[12];
  P.bb2  = (const float*)d_in[13];
  P.Wllr = (const float*)d_in[14];
  P.bllr = (const float*)d_in[15];
  P.emb  = (const float*)d_in[16];

  cudaFuncSetAttribute(scl_kernel, cudaFuncAttributeMaxDynamicSharedMemorySize,
                       (int)sizeof(Smem));
  scl_kernel<<<NB, 512, sizeof(Smem)>>>(P, y, f, (float*)d_out, out_size);
}

// round 6
// speedup vs baseline: 2.6150x; 1.0657x over previous
#include <cuda_runtime.h>

// SCL polar decoder, neural-MLP variant. Round 6:
//  - ALL activation tensors (E levels 0..6) live in shared memory; the global
//    g_E scratch and the A staging tile are deleted. E0 stores a single list
//    (provably identical across lists). Layer-1 reads LDS.128 directly from E
//    (chk input rows are 128 contiguous floats); layer-2 writes STS.128 to E.
//  - rows-per-thread template RT {4,2,1}; layer-2 k-split for small nodes
//  - uniform-list elimination before first info leaf
//  - ~202KB dynamic smem, 1 block/SM (grid=128 < 148 SMs)

#define NLIST 8
#define DE    64
#define HD    256
#define DU    16
#define NB    128

struct Params {
  const float *Wo1, *bo1, *Wo2, *bo2;
  const float *Wc1, *bc1, *Wc2, *bc2;
  const float *Wb1, *bb1, *Wb2, *bb2;
  const float *Wllr, *bllr, *emb;
};

// E buffer offsets inside the flat smem array (floats)
#define EO1   0        // 8*32*64 = 16384
#define EO2   16384    // 8*16*64 = 8192
#define EO3   24576    // 4096
#define EO4   28672    // 2048
#define EO5   30720    // 1024
#define EO6   31744    // 512
#define EO0   32256    // single list: 64*64 = 4096
#define EMBO  36352    // 2*16 = 32
#define YO    36384    // obs input staging: 64*4 = 256
#define EALLN 36640

__host__ __device__ constexpr int EOlvl(int L){
  return (L==0)?EO0:(L==1)?EO1:(L==2)?EO2:(L==3)?EO3:(L==4)?EO4:(L==5)?EO5:EO6;
}
__host__ __device__ constexpr int OOFFc(int k){ int o=0; for(int i=0;i<k;i++) o += 8*(64>>i); return o; }
__host__ __device__ constexpr int SOFFc(int k){ int o=0; for(int i=0;i<k;i++) o += 4*(64>>i); return o; }

struct __align__(16) Smem {
  float EALL[EALLN];   // all E levels + emb + y staging
  float Bh[32*260];    // hidden tile row-major [r][h], stride 260 (16B rows)
  float Part[2048];    // layer-2 k-split partials
  int   Uout[1016];
  int   Xout[1016];
  float Lout[1016];
  int   U1[504];
  int   X1[504];
  float L1f[504];
  int   Ord1[48];
  int   Ord2[8];
  int   Ret[8];
  float Pm[8];
  float PmNew[8];
  float Llr[8];
  float Abs[8];
  int   Hd[8];
  int   first_info;
};

struct RowOff { int e; int emb; };

__device__ __forceinline__ void fma4(float4& a, const float4& w, float x){
  a.x += w.x*x; a.y += w.y*x; a.z += w.z*x; a.w += w.w*x;
}

// ---------------- fused 2-layer MLP: K -> 256 -> 64, all-smem activations ----
// RT rows/thread in layer 1; tile = 8*RT rows; layer-2 k-split KS = 4/RT.
// rowoff(r) gives float offsets into sm.EALL: 128 (or K) contiguous e floats,
// plus (K==144) a 16-float emb segment.
template<int K, int RT, typename RowOffF>
__device__ void run_mlp_s(Smem& sm, int R,
    const float* __restrict__ W1, const float* __restrict__ b1,
    const float* __restrict__ W2, const float* __restrict__ b2,
    int EoutOff, RowOffF rowoff)
{
  constexpr int BST   = 260;
  constexpr int TILE  = 8*RT;
  constexpr int KS    = 4/RT;
  constexpr int KC    = HD/KS;
  constexpr int TPG   = 128*RT;
  constexpr int KMAIN = (K < 128) ? K : 128;

  const int tid = threadIdx.x;
  const int hq  = tid & 63;
  const int rg  = tid >> 6;
  const int g   = tid / TPG;
  const int loc = tid - g*TPG;
  const int cq  = loc & 15;
  const int r2  = loc >> 4;
  const float4 bb1 = ((const float4*)b1)[hq];
  const float4 bb2 = ((const float4*)b2)[cq];

  for (int r0 = 0; r0 < R; r0 += TILE) {
    // ---- layer 1: LDS.128 activations straight from E ----
    {
      float4 acc[RT];
      RowOff ro[RT];
      #pragma unroll
      for (int j=0;j<RT;j++){ acc[j] = bb1; ro[j] = rowoff(r0 + rg*RT + j); }
      #pragma unroll 2
      for (int k4 = 0; k4 < KMAIN; k4 += 4){
        float4 w0 = ((const float4*)(W1 + (k4  )*HD))[hq];
        float4 w1 = ((const float4*)(W1 + (k4+1)*HD))[hq];
        float4 w2 = ((const float4*)(W1 + (k4+2)*HD))[hq];
        float4 w3 = ((const float4*)(W1 + (k4+3)*HD))[hq];
        #pragma unroll
        for (int j=0;j<RT;j++){
          float4 xv = *(const float4*)&sm.EALL[ro[j].e + k4];
          fma4(acc[j], w0, xv.x);
          fma4(acc[j], w1, xv.y);
          fma4(acc[j], w2, xv.z);
          fma4(acc[j], w3, xv.w);
        }
      }
      if constexpr (K > 128){
        #pragma unroll
        for (int k4 = 128; k4 < K; k4 += 4){
          float4 w0 = ((const float4*)(W1 + (k4  )*HD))[hq];
          float4 w1 = ((const float4*)(W1 + (k4+1)*HD))[hq];
          float4 w2 = ((const float4*)(W1 + (k4+2)*HD))[hq];
          float4 w3 = ((const float4*)(W1 + (k4+3)*HD))[hq];
          #pragma unroll
          for (int j=0;j<RT;j++){
            float4 xv = *(const float4*)&sm.EALL[ro[j].emb + (k4-128)];
            fma4(acc[j], w0, xv.x);
            fma4(acc[j], w1, xv.y);
            fma4(acc[j], w2, xv.z);
            fma4(acc[j], w3, xv.w);
          }
        }
      }
      #pragma unroll
      for (int j=0;j<RT;j++){
        float4 v;
        v.x = fmaxf(acc[j].x,0.f); v.y = fmaxf(acc[j].y,0.f);
        v.z = fmaxf(acc[j].z,0.f); v.w = fmaxf(acc[j].w,0.f);
        *(float4*)&sm.Bh[(rg*RT + j)*BST + 4*hq] = v;
      }
    }
    __syncthreads();
    // ---- layer 2 (256 -> 64), k-split across KS groups ----
    {
      float4 acc = (KS == 1 || g == 0) ? bb2 : make_float4(0.f,0.f,0.f,0.f);
      const float* Bb = &sm.Bh[r2*BST + g*KC];
      const float* W2b = W2 + g*KC*64;
      #pragma unroll 4
      for (int k = 0; k < KC; k++){
        float  x = Bb[k];
        float4 w = ((const float4*)(W2b + k*64))[cq];
        fma4(acc, w, x);
      }
      if constexpr (KS == 1){
        *(float4*)&sm.EALL[EoutOff + (r0+r2)*64 + cq*4] = acc;
      } else {
        *(float4*)&sm.Part[(g*TILE + r2)*64 + cq*4] = acc;
        __syncthreads();
        if (tid < TPG){
          float4 s = *(const float4*)&sm.Part[r2*64 + cq*4];
          #pragma unroll
          for (int gg = 1; gg < KS; gg++){
            float4 p = *(const float4*)&sm.Part[(gg*TILE + r2)*64 + cq*4];
            s.x += p.x; s.y += p.y; s.z += p.z; s.w += p.w;
          }
          *(float4*)&sm.EALL[EoutOff + (r0+r2)*64 + cq*4] = s;
        }
      }
    }
    __syncthreads();
  }
}

// broadcast list 0 -> lists 1..7 within smem E buffer; cnt = half*64 (pow2)
__device__ void bcast_lists(Smem& sm, int off, int cnt)
{
  float4* E4 = (float4*)&sm.EALL[off];
  const int cnt4 = cnt >> 2;
  for (int i = threadIdx.x; i < 7*cnt4; i += 512)
    E4[cnt4 + i] = E4[i & (cnt4 - 1)];
  __syncthreads();
}

// ---------------- leaf ----------------
__device__ void do_leaf(Smem& sm, int leaf, const Params& P, const int* __restrict__ f)
{
  const int tid = threadIdx.x, warp = tid>>5, lane = tid&31;
  constexpr int O6 = OOFFc(6);
  if (warp < 8) {
    const float* e = &sm.EALL[EO6 + warp*64];
    float z0 = 0.f, z1 = 0.f;
    for (int c = lane; c < 64; c += 32){
      float v = e[c];
      z0 += v*P.Wllr[c*2];
      z1 += v*P.Wllr[c*2+1];
    }
    #pragma unroll
    for (int off=16; off; off>>=1){
      z0 += __shfl_xor_sync(0xffffffffu, z0, off);
      z1 += __shfl_xor_sync(0xffffffffu, z1, off);
    }
    if (lane == 0){
      z0 += P.bllr[0]; z1 += P.bllr[1];
      float m  = fmaxf(z0, z1);
      float e0 = expf(z0 - m), e1 = expf(z1 - m);
      float p1 = e1 / (e0 + e1);
      p1 = fminf(fmaxf(p1, 1e-6f), 1.0f - 1e-6f);
      float llr = logf(p1) - logf(1.0f - p1);
      sm.Llr[warp] = llr;
      sm.Abs[warp] = fabsf(llr);
      sm.Hd[warp]  = (z1 > z0) ? 1 : 0;
    }
  }
  __syncthreads();
  if (warp == 0){
    const int fv = f[leaf];
    if (fv != 2){
      if (lane < 8){
        sm.Xout[O6+lane] = fv; sm.Uout[O6+lane] = fv;
        sm.Lout[O6+lane] = sm.Llr[lane];
        if (sm.Hd[lane] != fv) sm.Pm[lane] += sm.Abs[lane];
        sm.Ret[lane] = lane;
      }
    } else {
      float pd = 1e30f; int hd = 0;
      if (lane < 16){
        int l = lane & 7;
        if (lane < 8){ pd = sm.Pm[l];             hd = sm.Hd[l];     }
        else         { pd = sm.Pm[l] + sm.Abs[l]; hd = 1 - sm.Hd[l]; }
      }
      int rank = 0;
      #pragma unroll
      for (int q = 0; q < 16; q++){
        float pq = __shfl_sync(0xffffffffu, pd, q);
        if (pq < pd || (pq == pd && q < lane)) rank++;
      }
      unsigned surv = __ballot_sync(0xffffffffu, lane < 16 && rank < 8);
      if (lane < 16 && rank < 8){
        int pos = __popc(surv & ((1u<<lane) - 1u));
        sm.Xout[O6+pos] = hd; sm.Uout[O6+pos] = hd;
        sm.PmNew[pos]   = pd;
        sm.Ret[pos]     = lane & 7;
      }
      __syncwarp();
      if (lane < 8){ sm.Pm[lane] = sm.PmNew[lane]; sm.Lout[O6+lane] = sm.Llr[lane]; }
    }
  }
  __syncthreads();
}

// ---------------- tree recursion ----------------
template<int NK, int LVL>
__device__ void decode_node(Smem& sm, int leaf_base, const Params& P, const int* __restrict__ f)
{
  if constexpr (NK == 1) {
    do_leaf(sm, leaf_base, P, f);
  } else {
    constexpr int half = NK/2;
    constexpr int R    = 8*half;
    constexpr int RTF  = (half >= 4) ? 4 : half;
    constexpr int RTU  = (half >= 32) ? 4 : (half >= 16) ? 2 : 1;
    constexpr int EKo  = EOlvl(LVL);
    constexpr int ENo  = EOlvl(LVL+1);
    constexpr int ON   = OOFFc(LVL+1);
    constexpr int OK   = OOFFc(LVL);
    constexpr int SK   = SOFFc(LVL);
    constexpr bool L0  = (LVL == 0);

    auto chkRow = [&](int r)->RowOff {
      int l = r / half, t = r - l*half;
      int e = L0 ? (EO0 + 2*t*64) : (EKo + (l*NK + 2*t)*64);
      return {e, 0};
    };
    const bool uc = (sm.first_info >= leaf_base);
    if (uc){
      run_mlp_s<2*DE, RTU>(sm, half, P.Wc1, P.bc1, P.Wc2, P.bc2, ENo, chkRow);
      bcast_lists(sm, ENo, half*64);
    } else {
      run_mlp_s<2*DE, RTF>(sm, R, P.Wc1, P.bc1, P.Wc2, P.bc2, ENo, chkRow);
    }

    decode_node<half, LVL+1>(sm, leaf_base, P, f);

    __syncthreads();
    for (int idx = threadIdx.x; idx < R; idx += 512){
      sm.U1[SK+idx]  = sm.Uout[ON+idx];
      sm.X1[SK+idx]  = sm.Xout[ON+idx];
      sm.L1f[SK+idx] = sm.Lout[ON+idx];
    }
    if (threadIdx.x < 8) sm.Ord1[LVL*8 + threadIdx.x] = sm.Ret[threadIdx.x];
    __syncthreads();

    auto bitRow = [&](int r)->RowOff {
      int l = r / half, t = r - l*half;
      int ol = sm.Ord1[LVL*8 + l];
      int e = L0 ? (EO0 + 2*t*64) : (EKo + (ol*NK + 2*t)*64);
      int bit = sm.X1[SK + l*half + t];
      return {e, EMBO + bit*DU};
    };
    const bool ub = (sm.first_info >= leaf_base + half);
    if (ub){
      run_mlp_s<2*DE+DU, RTU>(sm, half, P.Wb1, P.bb1, P.Wb2, P.bb2, ENo, bitRow);
      bcast_lists(sm, ENo, half*64);
    } else {
      run_mlp_s<2*DE+DU, RTF>(sm, R, P.Wb1, P.bb1, P.Wb2, P.bb2, ENo, bitRow);
    }

    decode_node<half, LVL+1>(sm, leaf_base + half, P, f);

    __syncthreads();
    if (threadIdx.x < 8) sm.Ord2[threadIdx.x] = sm.Ret[threadIdx.x];
    __syncthreads();
    for (int idx = threadIdx.x; idx < R; idx += 512){
      int l = idx / half, t = idx - l*half;
      int o2 = sm.Ord2[l];
      int   u1 = sm.U1[SK + o2*half + t];
      int   x1 = sm.X1[SK + o2*half + t];
      float l1 = sm.L1f[SK + o2*half + t];
      int   u2 = sm.Uout[ON + idx];
      int   x2 = sm.Xout[ON + idx];
      float l2 = sm.Lout[ON + idx];
      sm.Uout[OK + l*NK + t]        = u1;
      sm.Uout[OK + l*NK + half + t] = u2;
      sm.Lout[OK + l*NK + t]        = l1;
      sm.Lout[OK + l*NK + half + t] = l2;
      sm.Xout[OK + l*NK + 2*t]      = (x1 + x2) & 1;
      sm.Xout[OK + l*NK + 2*t + 1]  = x2;
    }
    __syncthreads();
    if (threadIdx.x < 8) sm.Ret[threadIdx.x] = sm.Ord1[LVL*8 + sm.Ord2[threadIdx.x]];
    __syncthreads();
  }
}

__global__ void __launch_bounds__(512, 1)
scl_kernel(Params P, const float* __restrict__ y, const int* __restrict__ f,
           float* __restrict__ out, int out_size)
{
  extern __shared__ char smem_raw[];
  Smem& sm = *reinterpret_cast<Smem*>(smem_raw);
  const int b = blockIdx.x, tid = threadIdx.x;
  if (tid < 8) sm.Pm[tid] = (tid == 0) ? 0.f : 1e8f;
  if (tid == 0){
    int fi = 64;
    for (int i = 0; i < 64; i++) if (f[i] == 2){ fi = i; break; }
    sm.first_info = fi;
  }
  if (tid < 32) sm.EALL[EMBO + tid] = P.emb[tid];       // 2x16 embedding table
  if (tid < 256) sm.EALL[YO + tid] = y[b*256 + tid];    // obs input rows
  __syncthreads();

  // observation MLP (K=4) -> E0 (single list)
  run_mlp_s<4, 4>(sm, 64, P.Wo1, P.bo1, P.Wo2, P.bo2, EO0,
    [&](int r)->RowOff { return {YO + r*4, 0}; });

  decode_node<64, 0>(sm, 0, P, f);

  if (tid == 0){
    int best = 0; float bv = sm.Pm[0];
    for (int l=1;l<8;l++) if (sm.Pm[l] < bv){ bv = sm.Pm[l]; best = l; }
    sm.Ord2[0] = best;
  }
  __syncthreads();
  const int best = sm.Ord2[0];

  if (out_size >= 8192 + 65536){
    for (int t = tid; t < 64; t += 512)
      out[b*64 + t] = (float)sm.Uout[best*64 + t];
    for (int idx = tid; idx < 512; idx += 512)
      out[8192 + b*512 + idx] = sm.Lout[idx];
  } else if (out_size == 8192){
    for (int t = tid; t < 64; t += 512)
      out[b*64 + t] = (float)sm.Uout[best*64 + t];
  } else {
    for (int idx = tid; idx < 512 && (b*512 + idx) < out_size; idx += 512)
      out[b*512 + idx] = sm.Lout[idx];
  }
}

extern "C" void kernel_launch(void* const* d_in, const int* in_sizes, int n_in,
                              void* d_out, int out_size)
{
  Params P;
  const float* y  = (const float*)d_in[0];
  const int*   f  = (const int*)  d_in[1];
  P.Wo1  = (const float*)d_in[2];
  P.bo1  = (const float*)d_in[3];
  P.Wo2  = (const float*)d_in[4];
  P.bo2  = (const float*)d_in[5];
  P.Wc1  = (const float*)d_in[6];
  P.bc1  = (const float*)d_in[7];
  P.Wc2  = (const float*)d_in[8];
  P.bc2  = (const float*)d_in[9];
  P.Wb1  = (const float*)d_in[10];
  P.bb1  = (const float*)d_in[11];
  P.Wb2  = (const float*)d_in[12];
  P.bb2  = (const float*)d_in[13];
  P.Wllr = (const float*)d_in[14];
  P.bllr = (const float*)d_in[15];
  P.emb  = (const float*)d_in[16];

  cudaFuncSetAttribute(scl_kernel, cudaFuncAttributeMaxDynamicSharedMemorySize,
                       (int)sizeof(Smem));
  scl_kernel<<<NB, 512, sizeof(Smem)>>>(P, y, f, (float*)d_out, out_size);
}

// round 7
// speedup vs baseline: 2.6659x; 1.0195x over previous
#include <cuda_runtime.h>

// SCL polar decoder, neural-MLP variant. Round 7 = Round 6 + packed f32x2
// FMA (Blackwell fma.rn.f32x2) in both MLP layers. Per-lane arithmetic and
// accumulation order identical to round 6 -> bit-identical results.
//  - all activations smem-resident (E levels 0..6), no global scratch
//  - rows-per-thread template RT {4,2,1}; layer-2 k-split for small nodes
//  - uniform-list elimination before first info leaf

#define NLIST 8
#define DE    64
#define HD    256
#define DU    16
#define NB    128

typedef unsigned long long u64t;

struct Params {
  const float *Wo1, *bo1, *Wo2, *bo2;
  const float *Wc1, *bc1, *Wc2, *bc2;
  const float *Wb1, *bb1, *Wb2, *bb2;
  const float *Wllr, *bllr, *emb;
};

// E buffer offsets inside the flat smem array (floats)
#define EO1   0        // 8*32*64 = 16384
#define EO2   16384    // 8*16*64 = 8192
#define EO3   24576    // 4096
#define EO4   28672    // 2048
#define EO5   30720    // 1024
#define EO6   31744    // 512
#define EO0   32256    // single list: 64*64 = 4096
#define EMBO  36352    // 2*16 = 32
#define YO    36384    // obs input staging: 64*4 = 256
#define EALLN 36640

__host__ __device__ constexpr int EOlvl(int L){
  return (L==0)?EO0:(L==1)?EO1:(L==2)?EO2:(L==3)?EO3:(L==4)?EO4:(L==5)?EO5:EO6;
}
__host__ __device__ constexpr int OOFFc(int k){ int o=0; for(int i=0;i<k;i++) o += 8*(64>>i); return o; }
__host__ __device__ constexpr int SOFFc(int k){ int o=0; for(int i=0;i<k;i++) o += 4*(64>>i); return o; }

struct __align__(16) Smem {
  float EALL[EALLN];   // all E levels + emb + y staging
  float Bh[32*260];    // hidden tile row-major [r][h], stride 260 (16B rows)
  float Part[2048];    // layer-2 k-split partials
  int   Uout[1016];
  int   Xout[1016];
  float Lout[1016];
  int   U1[504];
  int   X1[504];
  float L1f[504];
  int   Ord1[48];
  int   Ord2[8];
  int   Ret[8];
  float Pm[8];
  float PmNew[8];
  float Llr[8];
  float Abs[8];
  int   Hd[8];
  int   first_info;
};

struct RowOff { int e; int emb; };

// ---- packed f32x2 helpers ----
__device__ __forceinline__ u64t pack2(float x){
  u64t r;
  asm("mov.b64 %0, {%1, %1};" : "=l"(r) : "f"(x));
  return r;
}
__device__ __forceinline__ void ffma2(u64t& acc, u64t a, u64t b){
  asm("fma.rn.f32x2 %0, %1, %2, %0;" : "+l"(acc) : "l"(a), "l"(b));
}
__device__ __forceinline__ void unpack2(u64t v, float& lo, float& hi){
  asm("mov.b64 {%0, %1}, %2;" : "=f"(lo), "=f"(hi) : "l"(v));
}

// ---------------- fused 2-layer MLP: K -> 256 -> 64, all-smem activations ----
// RT rows/thread in layer 1; tile = 8*RT rows; layer-2 k-split KS = 4/RT.
template<int K, int RT, typename RowOffF>
__device__ void run_mlp_s(Smem& sm, int R,
    const float* __restrict__ W1, const float* __restrict__ b1,
    const float* __restrict__ W2, const float* __restrict__ b2,
    int EoutOff, RowOffF rowoff)
{
  constexpr int BST   = 260;
  constexpr int TILE  = 8*RT;
  constexpr int KS    = 4/RT;
  constexpr int KC    = HD/KS;
  constexpr int TPG   = 128*RT;
  constexpr int KMAIN = (K < 128) ? K : 128;

  const int tid = threadIdx.x;
  const int hq  = tid & 63;
  const int rg  = tid >> 6;
  const int g   = tid / TPG;
  const int loc = tid - g*TPG;
  const int cq  = loc & 15;
  const int r2  = loc >> 4;
  const ulonglong2 bb1p = ((const ulonglong2*)b1)[hq];
  const ulonglong2 bb2p = ((const ulonglong2*)b2)[cq];

  for (int r0 = 0; r0 < R; r0 += TILE) {
    // ---- layer 1: LDS.128 activations straight from E, FFMA2 math ----
    {
      ulonglong2 acc[RT];
      RowOff ro[RT];
      #pragma unroll
      for (int j=0;j<RT;j++){ acc[j] = bb1p; ro[j] = rowoff(r0 + rg*RT + j); }
      #pragma unroll 2
      for (int k4 = 0; k4 < KMAIN; k4 += 4){
        ulonglong2 w0 = ((const ulonglong2*)(W1 + (k4  )*HD))[hq];
        ulonglong2 w1 = ((const ulonglong2*)(W1 + (k4+1)*HD))[hq];
        ulonglong2 w2 = ((const ulonglong2*)(W1 + (k4+2)*HD))[hq];
        ulonglong2 w3 = ((const ulonglong2*)(W1 + (k4+3)*HD))[hq];
        #pragma unroll
        for (int j=0;j<RT;j++){
          float4 xv = *(const float4*)&sm.EALL[ro[j].e + k4];
          u64t d0 = pack2(xv.x); ffma2(acc[j].x, w0.x, d0); ffma2(acc[j].y, w0.y, d0);
          u64t d1 = pack2(xv.y); ffma2(acc[j].x, w1.x, d1); ffma2(acc[j].y, w1.y, d1);
          u64t d2 = pack2(xv.z); ffma2(acc[j].x, w2.x, d2); ffma2(acc[j].y, w2.y, d2);
          u64t d3 = pack2(xv.w); ffma2(acc[j].x, w3.x, d3); ffma2(acc[j].y, w3.y, d3);
        }
      }
      if constexpr (K > 128){
        #pragma unroll
        for (int k4 = 128; k4 < K; k4 += 4){
          ulonglong2 w0 = ((const ulonglong2*)(W1 + (k4  )*HD))[hq];
          ulonglong2 w1 = ((const ulonglong2*)(W1 + (k4+1)*HD))[hq];
          ulonglong2 w2 = ((const ulonglong2*)(W1 + (k4+2)*HD))[hq];
          ulonglong2 w3 = ((const ulonglong2*)(W1 + (k4+3)*HD))[hq];
          #pragma unroll
          for (int j=0;j<RT;j++){
            float4 xv = *(const float4*)&sm.EALL[ro[j].emb + (k4-128)];
            u64t d0 = pack2(xv.x); ffma2(acc[j].x, w0.x, d0); ffma2(acc[j].y, w0.y, d0);
            u64t d1 = pack2(xv.y); ffma2(acc[j].x, w1.x, d1); ffma2(acc[j].y, w1.y, d1);
            u64t d2 = pack2(xv.z); ffma2(acc[j].x, w2.x, d2); ffma2(acc[j].y, w2.y, d2);
            u64t d3 = pack2(xv.w); ffma2(acc[j].x, w3.x, d3); ffma2(acc[j].y, w3.y, d3);
          }
        }
      }
      #pragma unroll
      for (int j=0;j<RT;j++){
        float4 v;
        float f0,f1,f2,f3;
        unpack2(acc[j].x, f0, f1);
        unpack2(acc[j].y, f2, f3);
        v.x = fmaxf(f0,0.f); v.y = fmaxf(f1,0.f);
        v.z = fmaxf(f2,0.f); v.w = fmaxf(f3,0.f);
        *(float4*)&sm.Bh[(rg*RT + j)*BST + 4*hq] = v;
      }
    }
    __syncthreads();
    // ---- layer 2 (256 -> 64), k-split across KS groups, FFMA2 math ----
    {
      ulonglong2 acc2;
      if (KS == 1 || g == 0) acc2 = bb2p;
      else { acc2.x = 0ull; acc2.y = 0ull; }
      const float* Bb = &sm.Bh[r2*BST + g*KC];
      const float* W2b = W2 + g*KC*64;
      #pragma unroll 4
      for (int k = 0; k < KC; k++){
        u64t xd = pack2(Bb[k]);
        ulonglong2 w = ((const ulonglong2*)(W2b + k*64))[cq];
        ffma2(acc2.x, w.x, xd);
        ffma2(acc2.y, w.y, xd);
      }
      float4 acc;
      unpack2(acc2.x, acc.x, acc.y);
      unpack2(acc2.y, acc.z, acc.w);
      if constexpr (KS == 1){
        *(float4*)&sm.EALL[EoutOff + (r0+r2)*64 + cq*4] = acc;
      } else {
        *(float4*)&sm.Part[(g*TILE + r2)*64 + cq*4] = acc;
        __syncthreads();
        if (tid < TPG){
          float4 s = *(const float4*)&sm.Part[r2*64 + cq*4];
          #pragma unroll
          for (int gg = 1; gg < KS; gg++){
            float4 p = *(const float4*)&sm.Part[(gg*TILE + r2)*64 + cq*4];
            s.x += p.x; s.y += p.y; s.z += p.z; s.w += p.w;
          }
          *(float4*)&sm.EALL[EoutOff + (r0+r2)*64 + cq*4] = s;
        }
      }
    }
    __syncthreads();
  }
}

// broadcast list 0 -> lists 1..7 within smem E buffer; cnt = half*64 (pow2)
__device__ void bcast_lists(Smem& sm, int off, int cnt)
{
  float4* E4 = (float4*)&sm.EALL[off];
  const int cnt4 = cnt >> 2;
  for (int i = threadIdx.x; i < 7*cnt4; i += 512)
    E4[cnt4 + i] = E4[i & (cnt4 - 1)];
  __syncthreads();
}

// ---------------- leaf ----------------
__device__ void do_leaf(Smem& sm, int leaf, const Params& P, const int* __restrict__ f)
{
  const int tid = threadIdx.x, warp = tid>>5, lane = tid&31;
  constexpr int O6 = OOFFc(6);
  if (warp < 8) {
    const float* e = &sm.EALL[EO6 + warp*64];
    float z0 = 0.f, z1 = 0.f;
    for (int c = lane; c < 64; c += 32){
      float v = e[c];
      z0 += v*P.Wllr[c*2];
      z1 += v*P.Wllr[c*2+1];
    }
    #pragma unroll
    for (int off=16; off; off>>=1){
      z0 += __shfl_xor_sync(0xffffffffu, z0, off);
      z1 += __shfl_xor_sync(0xffffffffu, z1, off);
    }
    if (lane == 0){
      z0 += P.bllr[0]; z1 += P.bllr[1];
      float m  = fmaxf(z0, z1);
      float e0 = expf(z0 - m), e1 = expf(z1 - m);
      float p1 = e1 / (e0 + e1);
      p1 = fminf(fmaxf(p1, 1e-6f), 1.0f - 1e-6f);
      float llr = logf(p1) - logf(1.0f - p1);
      sm.Llr[warp] = llr;
      sm.Abs[warp] = fabsf(llr);
      sm.Hd[warp]  = (z1 > z0) ? 1 : 0;
    }
  }
  __syncthreads();
  if (warp == 0){
    const int fv = f[leaf];
    if (fv != 2){
      if (lane < 8){
        sm.Xout[O6+lane] = fv; sm.Uout[O6+lane] = fv;
        sm.Lout[O6+lane] = sm.Llr[lane];
        if (sm.Hd[lane] != fv) sm.Pm[lane] += sm.Abs[lane];
        sm.Ret[lane] = lane;
      }
    } else {
      float pd = 1e30f; int hd = 0;
      if (lane < 16){
        int l = lane & 7;
        if (lane < 8){ pd = sm.Pm[l];             hd = sm.Hd[l];     }
        else         { pd = sm.Pm[l] + sm.Abs[l]; hd = 1 - sm.Hd[l]; }
      }
      int rank = 0;
      #pragma unroll
      for (int q = 0; q < 16; q++){
        float pq = __shfl_sync(0xffffffffu, pd, q);
        if (pq < pd || (pq == pd && q < lane)) rank++;
      }
      unsigned surv = __ballot_sync(0xffffffffu, lane < 16 && rank < 8);
      if (lane < 16 && rank < 8){
        int pos = __popc(surv & ((1u<<lane) - 1u));
        sm.Xout[O6+pos] = hd; sm.Uout[O6+pos] = hd;
        sm.PmNew[pos]   = pd;
        sm.Ret[pos]     = lane & 7;
      }
      __syncwarp();
      if (lane < 8){ sm.Pm[lane] = sm.PmNew[lane]; sm.Lout[O6+lane] = sm.Llr[lane]; }
    }
  }
  __syncthreads();
}

// ---------------- tree recursion ----------------
template<int NK, int LVL>
__device__ void decode_node(Smem& sm, int leaf_base, const Params& P, const int* __restrict__ f)
{
  if constexpr (NK == 1) {
    do_leaf(sm, leaf_base, P, f);
  } else {
    constexpr int half = NK/2;
    constexpr int R    = 8*half;
    constexpr int RTF  = (half >= 4) ? 4 : half;
    constexpr int RTU  = (half >= 32) ? 4 : (half >= 16) ? 2 : 1;
    constexpr int EKo  = EOlvl(LVL);
    constexpr int ENo  = EOlvl(LVL+1);
    constexpr int ON   = OOFFc(LVL+1);
    constexpr int OK   = OOFFc(LVL);
    constexpr int SK   = SOFFc(LVL);
    constexpr bool L0  = (LVL == 0);

    auto chkRow = [&](int r)->RowOff {
      int l = r / half, t = r - l*half;
      int e = L0 ? (EO0 + 2*t*64) : (EKo + (l*NK + 2*t)*64);
      return {e, 0};
    };
    const bool uc = (sm.first_info >= leaf_base);
    if (uc){
      run_mlp_s<2*DE, RTU>(sm, half, P.Wc1, P.bc1, P.Wc2, P.bc2, ENo, chkRow);
      bcast_lists(sm, ENo, half*64);
    } else {
      run_mlp_s<2*DE, RTF>(sm, R, P.Wc1, P.bc1, P.Wc2, P.bc2, ENo, chkRow);
    }

    decode_node<half, LVL+1>(sm, leaf_base, P, f);

    __syncthreads();
    for (int idx = threadIdx.x; idx < R; idx += 512){
      sm.U1[SK+idx]  = sm.Uout[ON+idx];
      sm.X1[SK+idx]  = sm.Xout[ON+idx];
      sm.L1f[SK+idx] = sm.Lout[ON+idx];
    }
    if (threadIdx.x < 8) sm.Ord1[LVL*8 + threadIdx.x] = sm.Ret[threadIdx.x];
    __syncthreads();

    auto bitRow = [&](int r)->RowOff {
      int l = r / half, t = r - l*half;
      int ol = sm.Ord1[LVL*8 + l];
      int e = L0 ? (EO0 + 2*t*64) : (EKo + (ol*NK + 2*t)*64);
      int bit = sm.X1[SK + l*half + t];
      return {e, EMBO + bit*DU};
    };
    const bool ub = (sm.first_info >= leaf_base + half);
    if (ub){
      run_mlp_s<2*DE+DU, RTU>(sm, half, P.Wb1, P.bb1, P.Wb2, P.bb2, ENo, bitRow);
      bcast_lists(sm, ENo, half*64);
    } else {
      run_mlp_s<2*DE+DU, RTF>(sm, R, P.Wb1, P.bb1, P.Wb2, P.bb2, ENo, bitRow);
    }

    decode_node<half, LVL+1>(sm, leaf_base + half, P, f);

    __syncthreads();
    if (threadIdx.x < 8) sm.Ord2[threadIdx.x] = sm.Ret[threadIdx.x];
    __syncthreads();
    for (int idx = threadIdx.x; idx < R; idx += 512){
      int l = idx / half, t = idx - l*half;
      int o2 = sm.Ord2[l];
      int   u1 = sm.U1[SK + o2*half + t];
      int   x1 = sm.X1[SK + o2*half + t];
      float l1 = sm.L1f[SK + o2*half + t];
      int   u2 = sm.Uout[ON + idx];
      int   x2 = sm.Xout[ON + idx];
      float l2 = sm.Lout[ON + idx];
      sm.Uout[OK + l*NK + t]        = u1;
      sm.Uout[OK + l*NK + half + t] = u2;
      sm.Lout[OK + l*NK + t]        = l1;
      sm.Lout[OK + l*NK + half + t] = l2;
      sm.Xout[OK + l*NK + 2*t]      = (x1 + x2) & 1;
      sm.Xout[OK + l*NK + 2*t + 1]  = x2;
    }
    __syncthreads();
    if (threadIdx.x < 8) sm.Ret[threadIdx.x] = sm.Ord1[LVL*8 + sm.Ord2[threadIdx.x]];
    __syncthreads();
  }
}

__global__ void __launch_bounds__(512, 1)
scl_kernel(Params P, const float* __restrict__ y, const int* __restrict__ f,
           float* __restrict__ out, int out_size)
{
  extern __shared__ char smem_raw[];
  Smem& sm = *reinterpret_cast<Smem*>(smem_raw);
  const int b = blockIdx.x, tid = threadIdx.x;
  if (tid < 8) sm.Pm[tid] = (tid == 0) ? 0.f : 1e8f;
  if (tid == 0){
    int fi = 64;
    for (int i = 0; i < 64; i++) if (f[i] == 2){ fi = i; break; }
    sm.first_info = fi;
  }
  if (tid < 32) sm.EALL[EMBO + tid] = P.emb[tid];       // 2x16 embedding table
  if (tid < 256) sm.EALL[YO + tid] = y[b*256 + tid];    // obs input rows
  __syncthreads();

  // observation MLP (K=4) -> E0 (single list)
  run_mlp_s<4, 4>(sm, 64, P.Wo1, P.bo1, P.Wo2, P.bo2, EO0,
    [&](int r)->RowOff { return {YO + r*4, 0}; });

  decode_node<64, 0>(sm, 0, P, f);

  if (tid == 0){
    int best = 0; float bv = sm.Pm[0];
    for (int l=1;l<8;l++) if (sm.Pm[l] < bv){ bv = sm.Pm[l]; best = l; }
    sm.Ord2[0] = best;
  }
  __syncthreads();
  const int best = sm.Ord2[0];

  if (out_size >= 8192 + 65536){
    for (int t = tid; t < 64; t += 512)
      out[b*64 + t] = (float)sm.Uout[best*64 + t];
    for (int idx = tid; idx < 512; idx += 512)
      out[8192 + b*512 + idx] = sm.Lout[idx];
  } else if (out_size == 8192){
    for (int t = tid; t < 64; t += 512)
      out[b*64 + t] = (float)sm.Uout[best*64 + t];
  } else {
    for (int idx = tid; idx < 512 && (b*512 + idx) < out_size; idx += 512)
      out[b*512 + idx] = sm.Lout[idx];
  }
}

extern "C" void kernel_launch(void* const* d_in, const int* in_sizes, int n_in,
                              void* d_out, int out_size)
{
  Params P;
  const float* y  = (const float*)d_in[0];
  const int*   f  = (const int*)  d_in[1];
  P.Wo1  = (const float*)d_in[2];
  P.bo1  = (const float*)d_in[3];
  P.Wo2  = (const float*)d_in[4];
  P.bo2  = (const float*)d_in[5];
  P.Wc1  = (const float*)d_in[6];
  P.bc1  = (const float*)d_in[7];
  P.Wc2  = (const float*)d_in[8];
  P.bc2  = (const float*)d_in[9];
  P.Wb1  = (const float*)d_in[10];
  P.bb1  = (const float*)d_in[11];
  P.Wb2  = (const float*)d_in[12];
  P.bb2  = (const float*)d_in[13];
  P.Wllr = (const float*)d_in[14];
  P.bllr = (const float*)d_in[15];
  P.emb  = (const float*)d_in[16];

  cudaFuncSetAttribute(scl_kernel, cudaFuncAttributeMaxDynamicSharedMemorySize,
                       (int)sizeof(Smem));
  scl_kernel<<<NB, 512, sizeof(Smem)>>>(P, y, f, (float*)d_out, out_size);
}